// round 7
// baseline (speedup 1.0000x reference)
#include <cuda_runtime.h>

// ---------------- scratch (static device globals; no runtime alloc) ----------
__device__ float g_v[2*8*512*512];     // v = lrelu(conv_v(hrms))
__device__ float g_q[2*8*32*32];       // q = lrelu(conv_q(msi))
__device__ float g_k[2*128*32*32];     // k = lrelu(conv_k(hsi))
__device__ float g_kmax[2];            // per-sample max band norm of q
__device__ float g_att[2*8*128];       // softmax attention
__device__ float g_W2[2*8*9*128];      // folded weights [n][i][tap][c]

__device__ __forceinline__ float lrelu(float v) { return v >= 0.f ? v : 0.01f*v; }

// ---------------- conv_v: 8->8 ch, 3x3, stride 1, pad 1, on 512x512 ----------
__global__ void conv_v_kernel(const float* __restrict__ x,
                              const float* __restrict__ W,
                              const float* __restrict__ b) {
    __shared__ float Ws[8*9*8];   // [ic][tap][oc] (oc contiguous for float4)
    int tid = threadIdx.y*32 + threadIdx.x;
    for (int s = tid; s < 576; s += 256) {
        int oc = s & 7; int r = s >> 3; int t = r % 9; int ic = r / 9;
        Ws[s] = W[(oc*8 + ic)*9 + t];
    }
    __syncthreads();

    int gx = blockIdx.x*32 + threadIdx.x;
    int gy = blockIdx.y*8  + threadIdx.y;
    int n  = blockIdx.z;

    float acc[8];
    #pragma unroll
    for (int oc = 0; oc < 8; oc++) acc[oc] = __ldg(&b[oc]);

    const float* xb = x + n*8*512*512;
    #pragma unroll
    for (int ic = 0; ic < 8; ic++) {
        const float* p = xb + ic*512*512;
        #pragma unroll
        for (int ky = 0; ky < 3; ky++) {
            int iy = gy - 1 + ky;
            #pragma unroll
            for (int kx = 0; kx < 3; kx++) {
                int ix = gx - 1 + kx;
                float xv = 0.f;
                if ((unsigned)iy < 512u && (unsigned)ix < 512u) xv = p[iy*512 + ix];
                const float4* w4 = (const float4*)&Ws[(ic*9 + ky*3 + kx)*8];
                float4 wA = w4[0], wB = w4[1];
                acc[0] = fmaf(wA.x, xv, acc[0]);
                acc[1] = fmaf(wA.y, xv, acc[1]);
                acc[2] = fmaf(wA.z, xv, acc[2]);
                acc[3] = fmaf(wA.w, xv, acc[3]);
                acc[4] = fmaf(wB.x, xv, acc[4]);
                acc[5] = fmaf(wB.y, xv, acc[5]);
                acc[6] = fmaf(wB.z, xv, acc[6]);
                acc[7] = fmaf(wB.w, xv, acc[7]);
            }
        }
    }
    #pragma unroll
    for (int oc = 0; oc < 8; oc++)
        g_v[((n*8 + oc)*512 + gy)*512 + gx] = lrelu(acc[oc]);
}

// ---------------- conv_q: 8->8 ch, 3x3, stride 16, pad 1 -> 32x32 ------------
__global__ void conv_q_kernel(const float* __restrict__ x,
                              const float* __restrict__ W,
                              const float* __restrict__ b) {
    __shared__ float Ws[8*9*8];   // [ic][tap][oc]
    int tid = threadIdx.x;        // 32 threads
    for (int s = tid; s < 576; s += 32) {
        int oc = s & 7; int r = s >> 3; int t = r % 9; int ic = r / 9;
        Ws[s] = W[(oc*8 + ic)*9 + t];
    }
    __syncthreads();

    int ox = threadIdx.x;         // 0..31
    int oy = blockIdx.x;          // 0..31
    int n  = blockIdx.y;

    float acc[8];
    #pragma unroll
    for (int oc = 0; oc < 8; oc++) acc[oc] = __ldg(&b[oc]);

    int cy = oy*16 - 1, cx = ox*16 - 1;
    const float* xb = x + n*8*512*512;
    #pragma unroll
    for (int ic = 0; ic < 8; ic++) {
        const float* p = xb + ic*512*512;
        #pragma unroll
        for (int ky = 0; ky < 3; ky++) {
            int iy = cy + ky;
            #pragma unroll
            for (int kx = 0; kx < 3; kx++) {
                int ix = cx + kx;
                float xv = 0.f;
                if ((unsigned)iy < 512u && (unsigned)ix < 512u) xv = p[iy*512 + ix];
                const float4* w4 = (const float4*)&Ws[(ic*9 + ky*3 + kx)*8];
                float4 wA = w4[0], wB = w4[1];
                acc[0] = fmaf(wA.x, xv, acc[0]);
                acc[1] = fmaf(wA.y, xv, acc[1]);
                acc[2] = fmaf(wA.z, xv, acc[2]);
                acc[3] = fmaf(wA.w, xv, acc[3]);
                acc[4] = fmaf(wB.x, xv, acc[4]);
                acc[5] = fmaf(wB.y, xv, acc[5]);
                acc[6] = fmaf(wB.z, xv, acc[6]);
                acc[7] = fmaf(wB.w, xv, acc[7]);
            }
        }
    }
    #pragma unroll
    for (int oc = 0; oc < 8; oc++)
        g_q[(n*8 + oc)*1024 + oy*32 + ox] = lrelu(acc[oc]);
}

// ---------------- conv_k: 128->128 ch, 3x3, stride 4, pad 1 -> 32x32 ---------
// block (32 ox, 2 ty), each thread does 4 output channels; 8 oc per block.
__global__ void conv_k_kernel(const float* __restrict__ x,
                              const float* __restrict__ W,
                              const float* __restrict__ b) {
    __shared__ float Ws[128*9*8];  // [ic][tap][ocl] = 36 KB
    int tid = threadIdx.y*32 + threadIdx.x;   // 0..63
    int ocg = blockIdx.x;                     // 0..15
    int oy  = blockIdx.y;                     // 0..31
    int n   = blockIdx.z;

    for (int s = tid; s < 128*9*8; s += 64) {
        int ocl = s & 7; int r = s >> 3; int t = r % 9; int ic = r / 9;
        Ws[s] = W[((ocg*8 + ocl)*128 + ic)*9 + t];
    }
    __syncthreads();

    int ox  = threadIdx.x;
    int ocb = threadIdx.y*4;        // 0 or 4 (local)
    float acc[4];
    #pragma unroll
    for (int j = 0; j < 4; j++) acc[j] = __ldg(&b[ocg*8 + ocb + j]);

    int cy = oy*4 - 1, cx = ox*4 - 1;
    const float* xb = x + n*128*128*128;
    for (int ic = 0; ic < 128; ic++) {
        const float* p = xb + ic*128*128;
        float xv[9];
        #pragma unroll
        for (int ky = 0; ky < 3; ky++) {
            int iy = cy + ky;
            #pragma unroll
            for (int kx = 0; kx < 3; kx++) {
                int ix = cx + kx;
                float v = 0.f;
                if ((unsigned)iy < 128u && (unsigned)ix < 128u) v = p[iy*128 + ix];
                xv[ky*3 + kx] = v;
            }
        }
        #pragma unroll
        for (int t = 0; t < 9; t++) {
            float4 w = *(const float4*)&Ws[(ic*9 + t)*8 + ocb];
            acc[0] = fmaf(w.x, xv[t], acc[0]);
            acc[1] = fmaf(w.y, xv[t], acc[1]);
            acc[2] = fmaf(w.z, xv[t], acc[2]);
            acc[3] = fmaf(w.w, xv[t], acc[3]);
        }
    }
    #pragma unroll
    for (int j = 0; j < 4; j++) {
        int oc = ocg*8 + ocb + j;
        g_k[(n*128 + oc)*1024 + oy*32 + ox] = lrelu(acc[j]);
    }
}

// ---------------- k0_max: per-sample max over bands of ||q_band||_2 ----------
__global__ void kmax_kernel() {
    __shared__ float red[256];
    __shared__ float norms[8];
    int n = blockIdx.x, tid = threadIdx.x;
    for (int i = 0; i < 8; i++) {
        float s = 0.f;
        for (int idx = tid; idx < 1024; idx += 256) {
            float v = g_q[(n*8 + i)*1024 + idx];
            s = fmaf(v, v, s);
        }
        red[tid] = s; __syncthreads();
        for (int off = 128; off > 0; off >>= 1) {
            if (tid < off) red[tid] += red[tid + off];
            __syncthreads();
        }
        if (tid == 0) norms[i] = sqrtf(red[0]);
        __syncthreads();
    }
    if (tid == 0) {
        float m = norms[0];
        #pragma unroll
        for (int i = 1; i < 8; i++) m = fmaxf(m, norms[i]);
        g_kmax[n] = m;
    }
}

// ---------------- att + softmax: att[n,i,c] = <q[n,i]/kmax, k[n,c]> ----------
__global__ void att_kernel() {
    __shared__ float qs[1024];
    __shared__ float sm[128];
    int i = blockIdx.x, n = blockIdx.y, c = threadIdx.x;

    float inv = 1.f / g_kmax[n];
    for (int idx = c; idx < 1024; idx += 128)
        qs[idx] = g_q[(n*8 + i)*1024 + idx] * inv;
    __syncthreads();

    const float4* kc = (const float4*)&g_k[(n*128 + c)*1024];
    const float4* q4 = (const float4*)qs;
    float dot = 0.f;
    for (int idx = 0; idx < 256; idx++) {
        float4 a = q4[idx], bb = kc[idx];
        dot = fmaf(a.x, bb.x, dot);
        dot = fmaf(a.y, bb.y, dot);
        dot = fmaf(a.z, bb.z, dot);
        dot = fmaf(a.w, bb.w, dot);
    }
    float logit = dot * 10.f;

    sm[c] = logit; __syncthreads();
    for (int off = 64; off > 0; off >>= 1) {
        if (c < off) sm[c] = fmaxf(sm[c], sm[c + off]);
        __syncthreads();
    }
    float mx = sm[0]; __syncthreads();
    float e = __expf(logit - mx);
    sm[c] = e; __syncthreads();
    for (int off = 64; off > 0; off >>= 1) {
        if (c < off) sm[c] += sm[c + off];
        __syncthreads();
    }
    g_att[(n*8 + i)*128 + c] = e / sm[0];
}

// ---------------- W2[n,i,t,c] = (1/6) sum_c' Wr[c,c',t] * att[n,i,c'] --------
__global__ void w2_kernel(const float* __restrict__ Wr) {
    __shared__ float as[128];
    int t = blockIdx.x, i = blockIdx.y, n = blockIdx.z, c = threadIdx.x;
    as[c] = g_att[(n*8 + i)*128 + c];
    __syncthreads();
    float s = 0.f;
    for (int cp = 0; cp < 128; cp++)
        s = fmaf(__ldg(&Wr[(c*128 + cp)*9 + t]), as[cp], s);
    g_W2[((n*8 + i)*9 + t)*128 + c] = s * (1.f/6.f);
}

// ---------------- final fused kernel ----------------------------------------
// result[n,c,h,w] = lrelu( br[c] + sum_{i,dy,dx} W2[n,c,i,tap]*v[n,i,h-1+dy,w-1+dx] )
// Tile: 32x32 pixels, 8 channels per block. block(32 x, 8 rowgroups),
// each thread: 1 x-column, 4 rows, 8 channels -> 32 accumulators.
__global__ void __launch_bounds__(256)
final_kernel(float* __restrict__ out, const float* __restrict__ br) {
    __shared__ float Vs[8][34][34];    // v tile + halo
    __shared__ float Ws[8*8*12];       // [i][cl][tap padded to 12]
    __shared__ float bs[8];

    int tid = threadIdx.y*32 + threadIdx.x;
    int bz = blockIdx.z;
    int n  = bz >> 4;
    int cg = bz & 15;
    int cbase = cg * 8;
    int tx0 = blockIdx.x * 32;
    int ty0 = blockIdx.y * 32;

    // load v tile (zero halo at image border)
    for (int s = tid; s < 8*34*34; s += 256) {
        int xx = s % 34; int r = s / 34; int yy = r % 34; int i = r / 34;
        int gy = ty0 - 1 + yy, gx = tx0 - 1 + xx;
        float v = 0.f;
        if ((unsigned)gy < 512u && (unsigned)gx < 512u)
            v = g_v[((n*8 + i)*512 + gy)*512 + gx];
        Vs[i][yy][xx] = v;
    }
    // load folded weights for our 8 channels
    for (int s = tid; s < 576; s += 256) {
        int t = s % 9; int r = s / 9; int cl = r % 8; int i = r / 8;
        Ws[(i*8 + cl)*12 + t] = g_W2[((n*8 + i)*9 + t)*128 + cbase + cl];
    }
    if (tid < 8) bs[tid] = __ldg(&br[cbase + tid]);
    __syncthreads();

    int x  = threadIdx.x;        // column inside tile
    int rb = threadIdx.y * 4;    // first of 4 output rows

    float acc[8][4];
    #pragma unroll
    for (int cl = 0; cl < 8; cl++)
        #pragma unroll
        for (int p = 0; p < 4; p++) acc[cl][p] = 0.f;

    for (int i = 0; i < 8; i++) {
        // v column strip: rows rb..rb+5 (smem row = out_row_local + dy), cols x..x+2
        float vv[6][3];
        #pragma unroll
        for (int yy = 0; yy < 6; yy++)
            #pragma unroll
            for (int xx = 0; xx < 3; xx++)
                vv[yy][xx] = Vs[i][rb + yy][x + xx];

        #pragma unroll
        for (int cl = 0; cl < 8; cl++) {
            const float* wp = &Ws[(i*8 + cl)*12];
            float4 wA = *(const float4*)wp;
            float4 wB = *(const float4*)(wp + 4);
            float  w8 = wp[8];
            float w[9] = {wA.x, wA.y, wA.z, wA.w, wB.x, wB.y, wB.z, wB.w, w8};
            #pragma unroll
            for (int p = 0; p < 4; p++) {
                float a = acc[cl][p];
                #pragma unroll
                for (int dy = 0; dy < 3; dy++) {
                    a = fmaf(w[dy*3 + 0], vv[p + dy][0], a);
                    a = fmaf(w[dy*3 + 1], vv[p + dy][1], a);
                    a = fmaf(w[dy*3 + 2], vv[p + dy][2], a);
                }
                acc[cl][p] = a;
            }
        }
    }

    #pragma unroll
    for (int cl = 0; cl < 8; cl++) {
        int c = cbase + cl;
        float bb = bs[cl];
        #pragma unroll
        for (int p = 0; p < 4; p++) {
            float val = acc[cl][p] + bb;
            val = val >= 0.f ? val : 0.01f*val;
            out[((n*128 + c)*512 + (ty0 + rb + p))*512 + tx0 + x] = val;
        }
    }
}

// ---------------- launch ------------------------------------------------------
extern "C" void kernel_launch(void* const* d_in, const int* in_sizes, int n_in,
                              void* d_out, int out_size) {
    const float* hrms = (const float*)d_in[0];
    const float* msi  = (const float*)d_in[1];
    const float* hsi  = (const float*)d_in[2];
    const float* Wv   = (const float*)d_in[3];
    const float* bv   = (const float*)d_in[4];
    const float* Wq   = (const float*)d_in[5];
    const float* bq   = (const float*)d_in[6];
    const float* Wk   = (const float*)d_in[7];
    const float* bk   = (const float*)d_in[8];
    const float* Wr   = (const float*)d_in[9];
    const float* br   = (const float*)d_in[10];
    float* out = (float*)d_out;

    conv_v_kernel<<<dim3(16, 64, 2), dim3(32, 8)>>>(hrms, Wv, bv);
    conv_q_kernel<<<dim3(32, 2), 32>>>(msi, Wq, bq);
    conv_k_kernel<<<dim3(16, 32, 2), dim3(32, 2)>>>(hsi, Wk, bk);
    kmax_kernel<<<2, 256>>>();
    att_kernel<<<dim3(8, 2), 128>>>();
    w2_kernel<<<dim3(9, 8, 2), 128>>>(Wr);
    final_kernel<<<dim3(16, 16, 32), dim3(32, 8)>>>(out, br);
}

// round 9
// speedup vs baseline: 1.1497x; 1.1497x over previous
#include <cuda_runtime.h>

// ---------------- scratch (static device globals; no runtime alloc) ----------
__device__ float g_v[2*8*512*512];     // v = lrelu(conv_v(hrms))
__device__ float g_q[2*8*32*32];       // q = lrelu(conv_q(msi))
__device__ float g_k[2*128*32*32];     // k = lrelu(conv_k(hsi))
__device__ float g_att[2*8*128];       // softmax attention
__device__ float g_W2[2*8*9*128];      // folded weights [n][i][tap][c]

__device__ __forceinline__ float lrelu(float v) { return v >= 0.f ? v : 0.01f*v; }

// ---- packed f32x2 helpers (Blackwell packed FP32 pipe; 2 FMAs / instruction)
typedef unsigned long long ull;

__device__ __forceinline__ ull pack2(float lo, float hi) {
    ull r;
    asm("mov.b64 %0, {%1, %2};" : "=l"(r) : "f"(lo), "f"(hi));
    return r;
}
__device__ __forceinline__ void fma2(ull& d, ull a, ull b) {
    asm("fma.rn.f32x2 %0, %1, %2, %0;" : "+l"(d) : "l"(a), "l"(b));
}
__device__ __forceinline__ void unpack2(float& lo, float& hi, ull v) {
    asm("mov.b64 {%0, %1}, %2;" : "=f"(lo), "=f"(hi) : "l"(v));
}

// ---------------- conv_v: 8->8 ch, 3x3, stride 1, pad 1, on 512x512 ----------
// smem-tiled, f32x2 packed over output-channel pairs.
// block (32,8): thread = 1 column x 4 rows x 8 output channels.
__global__ void __launch_bounds__(256, 2)
conv_v_kernel(const float* __restrict__ x,
              const float* __restrict__ W,
              const float* __restrict__ b) {
    __shared__ __align__(16) float Vs[8][34][34];   // input tile + halo
    __shared__ __align__(16) float Wf[8*9*8];       // [(ic*9+t)*8 + oc]
    __shared__ float bs[8];

    int tid = threadIdx.y*32 + threadIdx.x;
    int n   = blockIdx.z;
    int tx0 = blockIdx.x * 32;
    int ty0 = blockIdx.y * 32;

    // load input tile with halo (zero padding at border)
    for (int s = tid; s < 8*34*34; s += 256) {
        int xx = s % 34; int r = s / 34; int yy = r % 34; int i = r / 34;
        int gy = ty0 - 1 + yy, gx = tx0 - 1 + xx;
        float v = 0.f;
        if ((unsigned)gy < 512u && (unsigned)gx < 512u)
            v = x[((n*8 + i)*512 + gy)*512 + gx];
        Vs[i][yy][xx] = v;
    }
    // weights: W layout [oc][ic][3][3] -> Wf[(ic*9+t)*8 + oc]
    for (int s = tid; s < 576; s += 256) {
        int oc = s & 7; int r = s >> 3; int t = r % 9; int ic = r / 9;
        Wf[(ic*9 + t)*8 + oc] = W[(oc*8 + ic)*9 + t];
    }
    if (tid < 8) bs[tid] = b[tid];
    __syncthreads();

    int xcol = threadIdx.x;
    int rb   = threadIdx.y * 4;

    ull acc[4][4];   // [oc-pair][row]
    #pragma unroll
    for (int cp = 0; cp < 4; cp++)
        #pragma unroll
        for (int p = 0; p < 4; p++) acc[cp][p] = 0ull;

    #pragma unroll
    for (int i = 0; i < 8; i++) {
        ull vsp[6][3];
        #pragma unroll
        for (int yy = 0; yy < 6; yy++)
            #pragma unroll
            for (int xx = 0; xx < 3; xx++) {
                float v = Vs[i][rb + yy][xcol + xx];
                vsp[yy][xx] = pack2(v, v);
            }
        #pragma unroll
        for (int cp = 0; cp < 4; cp++) {
            ull w[9];
            #pragma unroll
            for (int t = 0; t < 9; t++)
                w[t] = *(const ull*)&Wf[(i*9 + t)*8 + cp*2];
            #pragma unroll
            for (int p = 0; p < 4; p++)
                #pragma unroll
                for (int dy = 0; dy < 3; dy++) {
                    fma2(acc[cp][p], w[dy*3 + 0], vsp[p + dy][0]);
                    fma2(acc[cp][p], w[dy*3 + 1], vsp[p + dy][1]);
                    fma2(acc[cp][p], w[dy*3 + 2], vsp[p + dy][2]);
                }
        }
    }

    #pragma unroll
    for (int cp = 0; cp < 4; cp++) {
        float b0 = bs[2*cp], b1 = bs[2*cp + 1];
        #pragma unroll
        for (int p = 0; p < 4; p++) {
            float a0, a1;
            unpack2(a0, a1, acc[cp][p]);
            int gy = ty0 + rb + p, gx = tx0 + xcol;
            g_v[((n*8 + 2*cp    )*512 + gy)*512 + gx] = lrelu(a0 + b0);
            g_v[((n*8 + 2*cp + 1)*512 + gy)*512 + gx] = lrelu(a1 + b1);
        }
    }
}

// ---------------- conv_q: 8->8 ch, 3x3, stride 16, pad 1 -> 32x32 ------------
__global__ void conv_q_kernel(const float* __restrict__ x,
                              const float* __restrict__ W,
                              const float* __restrict__ b) {
    __shared__ __align__(16) float Ws[8*9*8];   // [ic][tap][oc]
    int tid = threadIdx.x;        // 32 threads
    for (int s = tid; s < 576; s += 32) {
        int oc = s & 7; int r = s >> 3; int t = r % 9; int ic = r / 9;
        Ws[s] = W[(oc*8 + ic)*9 + t];
    }
    __syncthreads();

    int ox = threadIdx.x;
    int oy = blockIdx.x;
    int n  = blockIdx.y;

    float acc[8];
    #pragma unroll
    for (int oc = 0; oc < 8; oc++) acc[oc] = __ldg(&b[oc]);

    int cy = oy*16 - 1, cx = ox*16 - 1;
    const float* xb = x + n*8*512*512;
    #pragma unroll
    for (int ic = 0; ic < 8; ic++) {
        const float* p = xb + ic*512*512;
        #pragma unroll
        for (int ky = 0; ky < 3; ky++) {
            int iy = cy + ky;
            #pragma unroll
            for (int kx = 0; kx < 3; kx++) {
                int ix = cx + kx;
                float xv = 0.f;
                if ((unsigned)iy < 512u && (unsigned)ix < 512u) xv = p[iy*512 + ix];
                const float4* w4 = (const float4*)&Ws[(ic*9 + ky*3 + kx)*8];
                float4 wA = w4[0], wB = w4[1];
                acc[0] = fmaf(wA.x, xv, acc[0]);
                acc[1] = fmaf(wA.y, xv, acc[1]);
                acc[2] = fmaf(wA.z, xv, acc[2]);
                acc[3] = fmaf(wA.w, xv, acc[3]);
                acc[4] = fmaf(wB.x, xv, acc[4]);
                acc[5] = fmaf(wB.y, xv, acc[5]);
                acc[6] = fmaf(wB.z, xv, acc[6]);
                acc[7] = fmaf(wB.w, xv, acc[7]);
            }
        }
    }
    #pragma unroll
    for (int oc = 0; oc < 8; oc++)
        g_q[(n*8 + oc)*1024 + oy*32 + ox] = lrelu(acc[oc]);
}

// ---------------- conv_k: 128->128 ch, 3x3, stride 4, pad 1 -> 32x32 ---------
// block (32 ox, 4 oy-rows), each thread computes 8 output channels (4 f32x2 pairs).
__global__ void __launch_bounds__(128)
conv_k_kernel(const float* __restrict__ x,
              const float* __restrict__ W,
              const float* __restrict__ b) {
    __shared__ __align__(16) float Ws[128*9*8];  // [ic][tap][ocl] = 36 KB
    int tid = threadIdx.y*32 + threadIdx.x;      // 0..127
    int ocg = blockIdx.x;                        // 0..15
    int n   = blockIdx.z;
    int oy  = blockIdx.y*4 + threadIdx.y;        // 0..31

    for (int s = tid; s < 128*9*8; s += 128) {
        int ocl = s & 7; int r = s >> 3; int t = r % 9; int ic = r / 9;
        Ws[s] = W[((ocg*8 + ocl)*128 + ic)*9 + t];
    }
    __syncthreads();

    int ox = threadIdx.x;
    ull acc[4];
    #pragma unroll
    for (int cp = 0; cp < 4; cp++)
        acc[cp] = pack2(__ldg(&b[ocg*8 + 2*cp]), __ldg(&b[ocg*8 + 2*cp + 1]));

    int cy = oy*4 - 1, cx = ox*4 - 1;
    const float* xb = x + n*128*128*128;
    for (int ic = 0; ic < 128; ic++) {
        const float* p = xb + ic*128*128;
        ull xs[9];
        #pragma unroll
        for (int ky = 0; ky < 3; ky++) {
            int iy = cy + ky;
            #pragma unroll
            for (int kx = 0; kx < 3; kx++) {
                int ix = cx + kx;
                float v = 0.f;
                if ((unsigned)iy < 128u && (unsigned)ix < 128u) v = p[iy*128 + ix];
                xs[ky*3 + kx] = pack2(v, v);
            }
        }
        #pragma unroll
        for (int t = 0; t < 9; t++) {
            const float* wrow = &Ws[(ic*9 + t)*8];
            #pragma unroll
            for (int cp = 0; cp < 4; cp++)
                fma2(acc[cp], *(const ull*)&wrow[2*cp], xs[t]);
        }
    }
    #pragma unroll
    for (int cp = 0; cp < 4; cp++) {
        float a0, a1;
        unpack2(a0, a1, acc[cp]);
        int oc = ocg*8 + 2*cp;
        g_k[(n*128 + oc    )*1024 + oy*32 + ox] = lrelu(a0);
        g_k[(n*128 + oc + 1)*1024 + oy*32 + ox] = lrelu(a1);
    }
}

// ---------------- att (+fused kmax): att[n,i,c] = softmax_c(10*<q/kmax, k_c>) -
__global__ void att_kernel() {
    __shared__ __align__(16) float qs[1024];
    __shared__ float red[128];
    int i = blockIdx.x, n = blockIdx.y, c = threadIdx.x;

    // kmax: max over bands of ||q_band||_2 (recomputed per block; tiny)
    float m = 0.f;
    for (int bnd = 0; bnd < 8; bnd++) {
        float s = 0.f;
        for (int idx = c; idx < 1024; idx += 128) {
            float v = g_q[(n*8 + bnd)*1024 + idx];
            s = fmaf(v, v, s);
        }
        red[c] = s; __syncthreads();
        for (int off = 64; off > 0; off >>= 1) {
            if (c < off) red[c] += red[c + off];
            __syncthreads();
        }
        m = fmaxf(m, sqrtf(red[0]));
        __syncthreads();
    }
    float inv = 1.f / m;

    for (int idx = c; idx < 1024; idx += 128)
        qs[idx] = g_q[(n*8 + i)*1024 + idx] * inv;
    __syncthreads();

    const float4* kc = (const float4*)&g_k[(n*128 + c)*1024];
    const float4* q4 = (const float4*)qs;
    float dot = 0.f;
    #pragma unroll 4
    for (int idx = 0; idx < 256; idx++) {
        float4 a = q4[idx], bb = kc[idx];
        dot = fmaf(a.x, bb.x, dot);
        dot = fmaf(a.y, bb.y, dot);
        dot = fmaf(a.z, bb.z, dot);
        dot = fmaf(a.w, bb.w, dot);
    }
    float logit = dot * 10.f;

    red[c] = logit; __syncthreads();
    for (int off = 64; off > 0; off >>= 1) {
        if (c < off) red[c] = fmaxf(red[c], red[c + off]);
        __syncthreads();
    }
    float mx = red[0]; __syncthreads();
    float e = __expf(logit - mx);
    red[c] = e; __syncthreads();
    for (int off = 64; off > 0; off >>= 1) {
        if (c < off) red[c] += red[c + off];
        __syncthreads();
    }
    g_att[(n*8 + i)*128 + c] = e / red[0];
}

// ---------------- W2[n,i,t,c] = (1/6) sum_c' Wr[c,c',t] * att[n,i,c'] --------
__global__ void w2_kernel(const float* __restrict__ Wr) {
    __shared__ float as[128];
    int t = blockIdx.x, i = blockIdx.y, n = blockIdx.z, c = threadIdx.x;
    as[c] = g_att[(n*8 + i)*128 + c];
    __syncthreads();
    float s = 0.f;
    #pragma unroll 4
    for (int cp = 0; cp < 128; cp++)
        s = fmaf(__ldg(&Wr[(c*128 + cp)*9 + t]), as[cp], s);
    g_W2[((n*8 + i)*9 + t)*128 + c] = s * (1.f/6.f);
}

// ---------------- final fused kernel (f32x2 packed over channel pairs) -------
// result[n,c,h,w] = lrelu( br[c] + sum_{i,dy,dx} W2[n,c,i,tap]*v[n,i,h-1+dy,w-1+dx] )
// Tile 32x32 pixels, 8 channels per block; thread = 1 col x 4 rows x 4 ch-pairs.
__global__ void __launch_bounds__(256, 2)
final_kernel(float* __restrict__ out, const float* __restrict__ br) {
    __shared__ __align__(16) float Vs[8][34][34];
    __shared__ __align__(16) float Wf[8*9*8];   // [(i*9+t)*8 + cl]
    __shared__ float bs[8];

    int tid = threadIdx.y*32 + threadIdx.x;
    int bz = blockIdx.z;
    int n  = bz >> 4;
    int cbase = (bz & 15) * 8;
    int tx0 = blockIdx.x * 32;
    int ty0 = blockIdx.y * 32;

    for (int s = tid; s < 8*34*34; s += 256) {
        int xx = s % 34; int r = s / 34; int yy = r % 34; int i = r / 34;
        int gy = ty0 - 1 + yy, gx = tx0 - 1 + xx;
        float v = 0.f;
        if ((unsigned)gy < 512u && (unsigned)gx < 512u)
            v = g_v[((n*8 + i)*512 + gy)*512 + gx];
        Vs[i][yy][xx] = v;
    }
    for (int s = tid; s < 576; s += 256) {
        int cl = s & 7; int r = s >> 3; int t = r % 9; int i = r / 9;
        Wf[(i*9 + t)*8 + cl] = g_W2[((n*8 + i)*9 + t)*128 + cbase + cl];
    }
    if (tid < 8) bs[tid] = __ldg(&br[cbase + tid]);
    __syncthreads();

    int xcol = threadIdx.x;
    int rb   = threadIdx.y * 4;

    ull acc[4][4];   // [channel-pair][row]
    #pragma unroll
    for (int cp = 0; cp < 4; cp++)
        #pragma unroll
        for (int p = 0; p < 4; p++) acc[cp][p] = 0ull;

    #pragma unroll
    for (int i = 0; i < 8; i++) {
        ull vsp[6][3];
        #pragma unroll
        for (int yy = 0; yy < 6; yy++)
            #pragma unroll
            for (int xx = 0; xx < 3; xx++) {
                float v = Vs[i][rb + yy][xcol + xx];
                vsp[yy][xx] = pack2(v, v);
            }
        #pragma unroll
        for (int cp = 0; cp < 4; cp++) {
            ull w[9];
            #pragma unroll
            for (int t = 0; t < 9; t++)
                w[t] = *(const ull*)&Wf[(i*9 + t)*8 + cp*2];
            #pragma unroll
            for (int p = 0; p < 4; p++)
                #pragma unroll
                for (int dy = 0; dy < 3; dy++) {
                    fma2(acc[cp][p], w[dy*3 + 0], vsp[p + dy][0]);
                    fma2(acc[cp][p], w[dy*3 + 1], vsp[p + dy][1]);
                    fma2(acc[cp][p], w[dy*3 + 2], vsp[p + dy][2]);
                }
        }
    }

    #pragma unroll
    for (int cp = 0; cp < 4; cp++) {
        int c0 = cbase + 2*cp;
        float b0 = bs[2*cp], b1 = bs[2*cp + 1];
        #pragma unroll
        for (int p = 0; p < 4; p++) {
            float a0, a1;
            unpack2(a0, a1, acc[cp][p]);
            int gy = ty0 + rb + p, gx = tx0 + xcol;
            float v0 = a0 + b0; v0 = v0 >= 0.f ? v0 : 0.01f*v0;
            float v1 = a1 + b1; v1 = v1 >= 0.f ? v1 : 0.01f*v1;
            out[((n*128 + c0    )*512 + gy)*512 + gx] = v0;
            out[((n*128 + c0 + 1)*512 + gy)*512 + gx] = v1;
        }
    }
}

// ---------------- launch ------------------------------------------------------
extern "C" void kernel_launch(void* const* d_in, const int* in_sizes, int n_in,
                              void* d_out, int out_size) {
    const float* hrms = (const float*)d_in[0];
    const float* msi  = (const float*)d_in[1];
    const float* hsi  = (const float*)d_in[2];
    const float* Wv   = (const float*)d_in[3];
    const float* bv   = (const float*)d_in[4];
    const float* Wq   = (const float*)d_in[5];
    const float* bq   = (const float*)d_in[6];
    const float* Wk   = (const float*)d_in[7];
    const float* bk   = (const float*)d_in[8];
    const float* Wr   = (const float*)d_in[9];
    const float* br   = (const float*)d_in[10];
    float* out = (float*)d_out;

    conv_v_kernel<<<dim3(16, 16, 2), dim3(32, 8)>>>(hrms, Wv, bv);
    conv_q_kernel<<<dim3(32, 2), 32>>>(msi, Wq, bq);
    conv_k_kernel<<<dim3(16, 8, 2), dim3(32, 4)>>>(hsi, Wk, bk);
    att_kernel<<<dim3(8, 2), 128>>>();
    w2_kernel<<<dim3(9, 8, 2), 128>>>(Wr);
    final_kernel<<<dim3(16, 16, 32), dim3(32, 8)>>>(out, br);
}